// round 10
// baseline (speedup 1.0000x reference)
#include <cuda_runtime.h>
#include <math.h>

// Problem constants
#define NB   2
#define NC   96
#define SP   64000          // 40*40*40
#define NHD  24             // head dim
#define NHEADS 4
#define LPB  4              // lines per attention block

typedef unsigned long long ull;

// -------- scratch buffers (global __device__, no allocation) --------
__device__ float g_tmp1[NB*NC*SP];     // conv3 output; later reused as oT_d
__device__ float g_t2  [NB*NC*SP];     // fused lp2+mod1 output; later reused as oT_h
__device__ float g_xmod[NB*NC*SP];     // x * mod
__device__ float g_qkv [NB*3*NC*SP];   // qkv native layout (q pre-scaled)
__device__ float g_qTd [NB*3*NC*SP];   // qkv transposed: d innermost
__device__ float g_qTh [NB*3*NC*SP];   // qkv transposed: h innermost
__device__ float g_osum[NB*NC*SP];     // sum of 3 axial attentions
__device__ float g_Wt  [NC*27*NC];     // lp1_w transposed -> [ci][tap][oc]
__device__ float g_Wc  [NC*NC];        // mod1_w @ lp2_w
__device__ float g_bc  [NC];
__device__ float g_mu1[NB*NC], g_rs1[NB*NC];
__device__ float g_mu2[NB*NC], g_rs2[NB*NC];

// -------- f32x2 packed helpers --------
union U2f { ull u; float2 f; };
__device__ __forceinline__ float2 asf2(ull a){ U2f t; t.u = a; return t.f; }
__device__ __forceinline__ ull pack2(float lo, float hi){
    ull r; asm("mov.b64 %0, {%1,%2};" : "=l"(r) : "f"(lo), "f"(hi)); return r;
}
__device__ __forceinline__ ull fma2(ull a, ull b, ull c){
    ull d; asm("fma.rn.f32x2 %0, %1, %2, %3;" : "=l"(d) : "l"(a), "l"(b), "l"(c)); return d;
}

__device__ __forceinline__ float gelu_f(float x){
    return 0.5f * x * (1.0f + erff(x * 0.70710678118654752f));
}

// -------- prep: Wc = mod1_w @ lp2_w ; bc = mod1_w @ lp2_b + mod1_b --------
__global__ void prep_wc_kernel(const float* __restrict__ mod1w,
                               const float* __restrict__ lp2w,
                               const float* __restrict__ lp2b,
                               const float* __restrict__ mod1b)
{
    int o = blockIdx.x;
    int i = threadIdx.x;
    float acc = 0.f;
    for (int k = 0; k < NC; k++)
        acc += mod1w[o*NC + k] * lp2w[k*NC + i];
    g_Wc[o*NC + i] = acc;
    if (i == 0) {
        float b = mod1b[o];
        for (int k = 0; k < NC; k++)
            b += mod1w[o*NC + k] * lp2b[k];
        g_bc[o] = b;
    }
}

// -------- prep: transpose lp1_w [oc][ci][27] -> Wt [ci][tap][oc] --------
// Split into 3 partial launches (also positions conv3 at ncu launch #6).
__global__ void prep_wt_kernel(const float* __restrict__ lp1w, int base)
{
    int idx = base + blockIdx.x * blockDim.x + threadIdx.x;
    if (idx >= NC*NC*27) return;
    int oc  = idx / (NC*27);
    int rem = idx - oc*(NC*27);
    int ci  = rem / 27;
    int tap = rem - ci*27;
    g_Wt[(ci*27 + tap)*NC + oc] = lp1w[idx];
}

// -------- tiny zero-init (harmless; stats overwrites). launch-count padding --------
__global__ void zero_small_kernel()
{
    int i = threadIdx.x;
    if (i < NB*NC) { g_mu1[i] = 0.f; g_rs1[i] = 0.f; }
}

// -------- conv3 circular (pos_emb -> g_tmp1), f32x2 packed (round-3 form) --------
__global__ void __launch_bounds__(96) conv3_kernel(const float* __restrict__ pin,
                                                   const float* __restrict__ bias)
{
    __shared__ __align__(16) float s_in[16*9*44];
    int y = blockIdx.x, z = blockIdx.y, b = blockIdx.z;
    int tid = threadIdx.x;

    ull acc[20];
    {
        float bv = bias[tid];
        ull bp = pack2(bv, bv);
        #pragma unroll
        for (int j = 0; j < 20; j++) acc[j] = bp;
    }

    for (int ch = 0; ch < 6; ch++) {
        __syncthreads();
        for (int idx = tid; idx < 16*9*42; idx += 96) {
            int ci  = idx / 378;
            int r   = idx - ci*378;
            int dzy = r / 42;
            int xx  = r - dzy*42;
            int dz = dzy / 3, dy = dzy - dz*3;
            int zz = z + dz - 1; zz += (zz < 0) ? 40 : 0; zz -= (zz >= 40) ? 40 : 0;
            int yy = y + dy - 1; yy += (yy < 0) ? 40 : 0; yy -= (yy >= 40) ? 40 : 0;
            int xw = xx - 1;     xw += (xw < 0) ? 40 : 0; xw -= (xw >= 40) ? 40 : 0;
            s_in[(ci*9 + dzy)*44 + xx] =
                pin[((size_t)(b*NC + ch*16 + ci)*40 + zz)*1600 + yy*40 + xw];
        }
        __syncthreads();

        for (int ci = 0; ci < 16; ci++) {
            for (int dzy = 0; dzy < 9; dzy++) {
                const float* wr = &g_Wt[(size_t)(((ch*16 + ci)*9 + dzy)*3)*NC + tid];
                float w0 = wr[0], w1 = wr[NC], w2 = wr[2*NC];
                ull W0 = pack2(w0, w0), W1 = pack2(w1, w1), W2 = pack2(w2, w2);
                const float* s = &s_in[(ci*9 + dzy)*44];
                ull a = *(const ull*)s;
                #pragma unroll
                for (int j = 0; j < 20; j++) {
                    ull bq = *(const ull*)(s + 2*j + 2);
                    float2 af = asf2(a), bf = asf2(bq);
                    ull d1 = pack2(af.y, bf.x);
                    acc[j] = fma2(W0, a,  acc[j]);
                    acc[j] = fma2(W1, d1, acc[j]);
                    acc[j] = fma2(W2, bq, acc[j]);
                    a = bq;
                }
            }
        }
    }

    float* outp = &g_tmp1[((size_t)(b*NC + tid)*40 + z)*1600 + y*40];
    #pragma unroll
    for (int j4 = 0; j4 < 10; j4++) {
        float2 p0 = asf2(acc[2*j4]);
        float2 p1 = asf2(acc[2*j4 + 1]);
        float4 o = make_float4(p0.x, p0.y, p1.x, p1.y);
        *(float4*)(outp + 4*j4) = o;
    }
}

// -------- instance-norm stats --------
__global__ void __launch_bounds__(512) stats_kernel(int sel)
{
    const float* src = sel ? g_t2 : g_tmp1;
    float* mu = sel ? g_mu2 : g_mu1;
    float* rs = sel ? g_rs2 : g_rs1;
    int bc = blockIdx.x;
    int tid = threadIdx.x;
    const float4* p = (const float4*)(src + (size_t)bc*SP);
    float s = 0.f, s2 = 0.f;
    for (int i = tid; i < SP/4; i += 512) {
        float4 v = p[i];
        s  += v.x + v.y + v.z + v.w;
        s2 += v.x*v.x + v.y*v.y + v.z*v.z + v.w*v.w;
    }
    for (int o = 16; o > 0; o >>= 1) {
        s  += __shfl_down_sync(0xffffffffu, s,  o);
        s2 += __shfl_down_sync(0xffffffffu, s2, o);
    }
    __shared__ float sh[2][16];
    int w = tid >> 5, l = tid & 31;
    if (l == 0) { sh[0][w] = s; sh[1][w] = s2; }
    __syncthreads();
    if (tid == 0) {
        float ts = 0.f, ts2 = 0.f;
        for (int i = 0; i < 16; i++) { ts += sh[0][i]; ts2 += sh[1][i]; }
        float m = ts * (1.0f/SP);
        float var = ts2 * (1.0f/SP) - m*m;
        mu[bc] = m;
        rs[bc] = rsqrtf(var + 1e-5f);
    }
}

// -------- pointwise GEMM with fused transforms (f32x2) --------
template<int MODE>
__global__ void __launch_bounds__(256) pw_kernel(const float* __restrict__ W,
                                                 const float* __restrict__ bias,
                                                 const float* __restrict__ xin,
                                                 float* __restrict__ outp)
{
    __shared__ __align__(16) float s_in[32*128];
    __shared__ float s_w [32*97];

    int t  = blockIdx.x;
    int b  = t / 500;
    int v0 = (t - b*500) * 128;
    int gy = blockIdx.y;
    int tid = threadIdx.x;

    const float* in  = (MODE==0) ? g_tmp1 : (MODE==1) ? g_t2 : (MODE==2) ? g_xmod : g_osum;
    const float* Wp  = (MODE==0) ? g_Wc : W;
    const float* bp  = (MODE==0) ? g_bc : bias;
    const float* mu  = (MODE==0) ? g_mu1 : g_mu2;
    const float* rs  = (MODE==0) ? g_rs1 : g_rs2;

    ull acc[6][4];
    #pragma unroll
    for (int i = 0; i < 6; i++)
        #pragma unroll
        for (int j = 0; j < 4; j++) acc[i][j] = 0ull;

    int ocg = tid >> 4;          // 0..15
    int vb  = (tid & 15) * 8;    // 0..120

    for (int kc = 0; kc < 3; kc++) {
        __syncthreads();
        for (int idx = tid; idx < 32*128; idx += 256) {
            int cil = idx >> 7, vv = idx & 127;
            int ci = kc*32 + cil;
            float val = in[((size_t)(b*NC + ci))*SP + v0 + vv];
            if (MODE == 0 || MODE == 1) {
                val = (val - mu[b*NC + ci]) * rs[b*NC + ci];
                val = gelu_f(val);
            }
            s_in[cil*128 + vv] = val;
        }
        for (int idx = tid; idx < 32*96; idx += 256) {
            int oc = idx >> 5, cil = idx & 31;
            s_w[cil*97 + oc] = Wp[(size_t)(gy*NC + oc)*NC + kc*32 + cil];
        }
        __syncthreads();

        #pragma unroll 4
        for (int kl = 0; kl < 32; kl++) {
            ull A[6];
            #pragma unroll
            for (int i = 0; i < 6; i++) {
                float av = s_w[kl*97 + ocg + 16*i];
                A[i] = pack2(av, av);
            }
            const ulonglong2* bp2 = (const ulonglong2*)&s_in[kl*128 + vb];
            ulonglong2 b01 = bp2[0];
            ulonglong2 b23 = bp2[1];
            #pragma unroll
            for (int i = 0; i < 6; i++) {
                acc[i][0] = fma2(A[i], b01.x, acc[i][0]);
                acc[i][1] = fma2(A[i], b01.y, acc[i][1]);
                acc[i][2] = fma2(A[i], b23.x, acc[i][2]);
                acc[i][3] = fma2(A[i], b23.y, acc[i][3]);
            }
        }
    }

    #pragma unroll
    for (int i = 0; i < 6; i++) {
        int oc  = ocg + 16*i;
        int goc = gy*NC + oc;
        float bb = bp[goc];
        #pragma unroll
        for (int jp = 0; jp < 4; jp++) {
            float2 f = asf2(acc[i][jp]);
            float rv[2] = {f.x + bb, f.y + bb};
            #pragma unroll
            for (int h = 0; h < 2; h++) {
                int j = jp*2 + h;
                float r = rv[h];
                size_t vidx = (size_t)v0 + vb + j;
                if (MODE == 0) {
                    g_t2[((size_t)(b*NC + oc))*SP + vidx] = r;
                } else if (MODE == 1) {
                    float m = 1.0f / (1.0f + expf(-r));
                    size_t o = ((size_t)(b*NC + oc))*SP + vidx;
                    g_xmod[o] = xin[o] * m;
                } else if (MODE == 2) {
                    if (goc < NC) r *= 0.20412414523193154f;   // 1/sqrt(24)
                    g_qkv[((size_t)(b*3*NC + goc))*SP + vidx] = r;
                } else {
                    outp[((size_t)(b*NC + oc))*SP + vidx] = r;
                }
            }
        }
    }
}

// -------- transposes: per-channel layout rotation, fully coalesced --------
__global__ void __launch_bounds__(256) tr_d_kernel(const float* __restrict__ in,
                                                   float* __restrict__ out)
{
    __shared__ float tile[40*33];
    int m0 = blockIdx.x * 32;
    size_t base = (size_t)blockIdx.y * SP;
    int tid = threadIdx.x;
    for (int idx = tid; idx < 1280; idx += 256) {
        int z = idx >> 5, mm = idx & 31;
        tile[z*33 + mm] = in[base + (size_t)z*1600 + m0 + mm];
    }
    __syncthreads();
    for (int idx = tid; idx < 1280; idx += 256) {
        int mm = idx / 40, z = idx - mm*40;
        out[base + (size_t)(m0 + mm)*40 + z] = tile[z*33 + mm];
    }
}

__global__ void __launch_bounds__(256) trb_d_kernel(const float* __restrict__ oT,
                                                    float* __restrict__ osum)
{
    __shared__ float tile[40*33];
    int m0 = blockIdx.x * 32;
    size_t base = (size_t)blockIdx.y * SP;
    int tid = threadIdx.x;
    for (int idx = tid; idx < 1280; idx += 256) {
        int mm = idx / 40, z = idx - mm*40;
        tile[z*33 + mm] = oT[base + (size_t)(m0 + mm)*40 + z];
    }
    __syncthreads();
    for (int idx = tid; idx < 1280; idx += 256) {
        int z = idx >> 5, mm = idx & 31;
        osum[base + (size_t)z*1600 + m0 + mm] += tile[z*33 + mm];
    }
}

__global__ void __launch_bounds__(256) tr_h_kernel(const float* __restrict__ in,
                                                   float* __restrict__ out)
{
    __shared__ float tile[40*41];
    int z = blockIdx.x;
    size_t base = (size_t)blockIdx.y * SP;
    int tid = threadIdx.x;
    for (int idx = tid; idx < 1600; idx += 256) {
        int y = idx / 40, x = idx - y*40;
        tile[y*41 + x] = in[base + (size_t)z*1600 + y*40 + x];
    }
    __syncthreads();
    for (int idx = tid; idx < 1600; idx += 256) {
        int x = idx / 40, y = idx - x*40;
        out[base + ((size_t)z*40 + x)*40 + y] = tile[y*41 + x];
    }
}

__global__ void __launch_bounds__(256) trb_h_kernel(const float* __restrict__ oT,
                                                    float* __restrict__ osum)
{
    __shared__ float tile[40*41];
    int z = blockIdx.x;
    size_t base = (size_t)blockIdx.y * SP;
    int tid = threadIdx.x;
    for (int idx = tid; idx < 1600; idx += 256) {
        int x = idx / 40, y = idx - x*40;
        tile[y*41 + x] = oT[base + ((size_t)z*40 + x)*40 + y];
    }
    __syncthreads();
    for (int idx = tid; idx < 1600; idx += 256) {
        int y = idx / 40, x = idx - y*40;
        osum[base + (size_t)z*1600 + y*40 + x] += tile[y*41 + x];
    }
}

// -------- axial attention: register-resident per-query rows --------
// Block: LPB lines of one (b,head). Thread (ll,i): query row i of line ll.
// q and S live in registers; k,v in smem read as warp-broadcast LDS.64.
__global__ void __launch_bounds__(40*LPB) attn_kernel(const float* __restrict__ src,
                                                      float* __restrict__ dst)
{
    __shared__ __align__(16) float skv[2][LPB][40*26];   // [k/v][line][l*26+dd]
    int b = blockIdx.z, head = blockIdx.y;
    int line0 = blockIdx.x * LPB;
    int tid = threadIdx.x;
    int ll = tid / 40;
    int i  = tid % 40;

    // load k,v coalesced: float4 over l, scatter to [l][dd]
    for (int idx = tid; idx < 2*LPB*24*10; idx += 40*LPB) {
        int w_ = idx / (LPB*240);
        int r  = idx - w_*(LPB*240);
        int l_ = r / 240;
        int r2 = r - l_*240;
        int dd = r2 / 10;
        int seg = r2 - dd*10;
        const float* p = src + ((size_t)(b*288 + (w_+1)*96 + head*NHD + dd))*SP
                             + (size_t)(line0 + l_)*40 + seg*4;
        float4 v4 = *(const float4*)p;
        float* d = &skv[w_][l_][0];
        int l4 = seg*4;
        d[(l4+0)*26 + dd] = v4.x;
        d[(l4+1)*26 + dd] = v4.y;
        d[(l4+2)*26 + dd] = v4.z;
        d[(l4+3)*26 + dd] = v4.w;
    }

    // load q row into registers (coalesced across i within a line)
    ull qr[12];
    {
        const float* qp = src + ((size_t)(b*288 + head*NHD))*SP
                              + (size_t)(line0 + ll)*40 + i;
        #pragma unroll
        for (int dp = 0; dp < 12; dp++)
            qr[dp] = pack2(qp[(size_t)(2*dp)*SP], qp[(size_t)(2*dp+1)*SP]);
    }
    __syncthreads();

    // scores
    float S[40];
    {
        const float* kb = &skv[0][ll][0];
        #pragma unroll 4
        for (int j = 0; j < 40; j++) {
            ull acc = 0ull;
            #pragma unroll
            for (int dp = 0; dp < 12; dp++)
                acc = fma2(qr[dp], *(const ull*)&kb[j*26 + 2*dp], acc);
            float2 f = asf2(acc);
            S[j] = f.x + f.y;
        }
    }

    // thread-local softmax (normalization folded into output)
    float m = -1e30f;
    #pragma unroll 8
    for (int j = 0; j < 40; j++) m = fmaxf(m, S[j]);
    float sum = 0.f;
    #pragma unroll 8
    for (int j = 0; j < 40; j++) { float e = __expf(S[j] - m); S[j] = e; sum += e; }
    float inv = 1.0f / sum;

    // output = (1/sum) * sum_j e_j * v_j
    ull o[12];
    #pragma unroll
    for (int dp = 0; dp < 12; dp++) o[dp] = 0ull;
    {
        const float* vb = &skv[1][ll][0];
        #pragma unroll 4
        for (int j = 0; j < 40; j++) {
            ull sj = pack2(S[j], S[j]);
            #pragma unroll
            for (int dp = 0; dp < 12; dp++)
                o[dp] = fma2(sj, *(const ull*)&vb[j*26 + 2*dp], o[dp]);
        }
    }

    size_t ob = ((size_t)(b*NC + head*NHD))*SP + (size_t)(line0 + ll)*40 + i;
    #pragma unroll
    for (int dp = 0; dp < 12; dp++) {
        float2 f = asf2(o[dp]);
        dst[ob + (size_t)(2*dp)*SP]   = f.x * inv;
        dst[ob + (size_t)(2*dp+1)*SP] = f.y * inv;
    }
}

// -------- launch --------
extern "C" void kernel_launch(void* const* d_in, const int* in_sizes, int n_in,
                              void* d_out, int out_size)
{
    const float* x      = (const float*)d_in[0];
    const float* pos    = (const float*)d_in[1];
    const float* qkv_w  = (const float*)d_in[2];
    const float* qkv_b  = (const float*)d_in[3];
    const float* lp1_w  = (const float*)d_in[4];
    const float* lp1_b  = (const float*)d_in[5];
    const float* lp2_w  = (const float*)d_in[6];
    const float* lp2_b  = (const float*)d_in[7];
    const float* mod1_w = (const float*)d_in[8];
    const float* mod1_b = (const float*)d_in[9];
    const float* mod2_w = (const float*)d_in[10];
    const float* mod2_b = (const float*)d_in[11];
    // d_in[12..16]: pa_w, pa_b, R6_d, R6_h, R6_w -- mathematically dead
    const float* proj_w = (const float*)d_in[17];
    const float* proj_b = (const float*)d_in[18];
    float* out = (float*)d_out;

    // 5 launches before conv3 so ncu (-s 5 -c 1) profiles conv3 next round
    prep_wc_kernel<<<96, 96>>>(mod1_w, lp2_w, lp2_b, mod1_b);
    const int WT_N = NC*NC*27, WT_P = (WT_N + 2) / 3;
    prep_wt_kernel<<<(WT_P + 255)/256, 256>>>(lp1_w, 0);
    prep_wt_kernel<<<(WT_P + 255)/256, 256>>>(lp1_w, WT_P);
    prep_wt_kernel<<<(WT_P + 255)/256, 256>>>(lp1_w, 2*WT_P);
    zero_small_kernel<<<1, 256>>>();

    conv3_kernel<<<dim3(40, 40, NB), 96>>>(pos, lp1_b);

    stats_kernel<<<NB*NC, 512>>>(0);
    pw_kernel<0><<<dim3(1000, 1), 256>>>(nullptr, nullptr, nullptr, nullptr);
    stats_kernel<<<NB*NC, 512>>>(1);
    pw_kernel<1><<<dim3(1000, 1), 256>>>(mod2_w, mod2_b, x, nullptr);
    pw_kernel<2><<<dim3(1000, 3), 256>>>(qkv_w, qkv_b, nullptr, nullptr);

    float* qTd = nullptr; float* qTh = nullptr;
    cudaGetSymbolAddress((void**)&qTd, g_qTd);
    cudaGetSymbolAddress((void**)&qTh, g_qTh);
    float* qkvp = nullptr; cudaGetSymbolAddress((void**)&qkvp, g_qkv);
    float* oTd = nullptr; cudaGetSymbolAddress((void**)&oTd, g_tmp1);  // reuse
    float* oTh = nullptr; cudaGetSymbolAddress((void**)&oTh, g_t2);    // reuse
    float* osum = nullptr; cudaGetSymbolAddress((void**)&osum, g_osum);

    tr_d_kernel<<<dim3(50, NB*3*NC), 256>>>(qkvp, qTd);
    tr_h_kernel<<<dim3(40, NB*3*NC), 256>>>(qkvp, qTh);

    attn_kernel<<<dim3(1600/LPB, NHEADS, NB), 40*LPB>>>(qkvp, osum);
    attn_kernel<<<dim3(1600/LPB, NHEADS, NB), 40*LPB>>>(qTd, oTd);
    attn_kernel<<<dim3(1600/LPB, NHEADS, NB), 40*LPB>>>(qTh, oTh);

    trb_d_kernel<<<dim3(50, NB*NC), 256>>>(oTd, osum);
    trb_h_kernel<<<dim3(40, NB*NC), 256>>>(oTh, osum);

    pw_kernel<3><<<dim3(1000, 1), 256>>>(proj_w, proj_b, nullptr, out);
}

// round 14
// speedup vs baseline: 1.5320x; 1.5320x over previous
#include <cuda_runtime.h>
#include <cuda_bf16.h>
#include <math.h>
#include <stdint.h>

#define NB   2
#define NC   96
#define SP   64000
#define NHD  24
#define NHEADS 4
#define LPB  4
#define BROW 104   // bf16 elements per B smem row (208 bytes, 52 banks -> conflict-free)

typedef unsigned long long ull;

// -------- scratch (no allocation) --------
__device__ float g_tmp1[NB*NC*SP];
__device__ float g_t2  [NB*NC*SP];
__device__ float g_xmod[NB*NC*SP];
__device__ float g_qkv [NB*3*NC*SP];
__device__ float g_qTd [NB*3*NC*SP];
__device__ float g_qTh [NB*3*NC*SP];
__device__ float g_osum[NB*NC*SP];
__device__ float g_Wc  [NC*NC];
__device__ float g_bc  [NC];
__device__ float g_mu1[NB*NC], g_rs1[NB*NC];
__device__ float g_mu2[NB*NC], g_rs2[NB*NC];
// conv operands: transposed wrap-padded input [b][z40][y42][x42][ci96], bf16 hi/lo
__device__ __align__(16) __nv_bfloat16 g_cTH[NB*40*42*42*96];
__device__ __align__(16) __nv_bfloat16 g_cTL[NB*40*42*42*96];
// weights [tap27][oc96][ci96] bf16 hi/lo
__device__ __align__(16) __nv_bfloat16 g_wTH[27*96*96];
__device__ __align__(16) __nv_bfloat16 g_wTL[27*96*96];

// -------- f32x2 helpers --------
union U2f { ull u; float2 f; };
__device__ __forceinline__ float2 asf2(ull a){ U2f t; t.u = a; return t.f; }
__device__ __forceinline__ ull pack2(float lo, float hi){
    ull r; asm("mov.b64 %0, {%1,%2};" : "=l"(r) : "f"(lo), "f"(hi)); return r;
}
__device__ __forceinline__ ull fma2(ull a, ull b, ull c){
    ull d; asm("fma.rn.f32x2 %0, %1, %2, %3;" : "=l"(d) : "l"(a), "l"(b), "l"(c)); return d;
}
__device__ __forceinline__ float gelu_f(float x){
    return 0.5f * x * (1.0f + erff(x * 0.70710678118654752f));
}

// warp mma: D(16x8) += A(16x16,row) * B(16x8,col), bf16 in, f32 acc
__device__ __forceinline__ void mma16816(float* c, const uint32_t* a, uint32_t b0, uint32_t b1){
    asm volatile("mma.sync.aligned.m16n8k16.row.col.f32.bf16.bf16.f32 "
        "{%0,%1,%2,%3}, {%4,%5,%6,%7}, {%8,%9}, {%0,%1,%2,%3};"
        : "+f"(c[0]), "+f"(c[1]), "+f"(c[2]), "+f"(c[3])
        : "r"(a[0]), "r"(a[1]), "r"(a[2]), "r"(a[3]), "r"(b0), "r"(b1));
}

// -------- preps --------
__global__ void prep_wc_kernel(const float* __restrict__ mod1w, const float* __restrict__ lp2w,
                               const float* __restrict__ lp2b, const float* __restrict__ mod1b)
{
    int o = blockIdx.x, i = threadIdx.x;
    float acc = 0.f;
    for (int k = 0; k < NC; k++) acc += mod1w[o*NC + k] * lp2w[k*NC + i];
    g_Wc[o*NC + i] = acc;
    if (i == 0) {
        float b = mod1b[o];
        for (int k = 0; k < NC; k++) b += mod1w[o*NC + k] * lp2b[k];
        g_bc[o] = b;
    }
}

__global__ void prep_wT_kernel(const float* __restrict__ lp1w)
{
    int i = blockIdx.x*256 + threadIdx.x;
    if (i >= 27*96*96) return;
    int tap = i / 9216, r2 = i - tap*9216, oc = r2 / 96, ci = r2 - oc*96;
    float w = lp1w[oc*2592 + ci*27 + tap];
    __nv_bfloat16 h = __float2bfloat16(w);
    g_wTH[i] = h;
    g_wTL[i] = __float2bfloat16(w - __bfloat162float(h));
}

// transpose + wrap-pad pos_emb: out[b][z][yp][xp][ci], yp/xp in 0..41 map to (j-1) mod 40
__global__ void prep_cT_kernel(const float* __restrict__ pos)
{
    __shared__ float tile[96*42];
    int yp = blockIdx.x, z = blockIdx.y, b = blockIdx.z;
    int ys = (yp + 39) % 40;
    int tid = threadIdx.x;
    for (int i = tid; i < 96*42; i += 256) {
        int ci = i / 42, xp = i - ci*42;
        int xs = (xp + 39) % 40;
        tile[ci*42 + xp] = pos[((size_t)(b*NC + ci)*40 + z)*1600 + ys*40 + xs];
    }
    __syncthreads();
    size_t dbase = (((size_t)b*40 + z)*42 + yp)*42*96;
    for (int i = tid; i < 96*42; i += 256) {
        int xp = i / 96, ci = i - xp*96;
        float v = tile[ci*42 + xp];
        __nv_bfloat16 h = __float2bfloat16(v);
        g_cTH[dbase + xp*96 + ci] = h;
        g_cTL[dbase + xp*96 + ci] = __float2bfloat16(v - __bfloat162float(h));
    }
}

// -------- conv3 via mma.sync: 27 shifted 1x1 GEMMs, 3-term bf16 split --------
// block: 192 thr (6 warps), (b, z, 4 y-rows). M=96 (warp m16), N=160, K=96/tap.
__global__ void __launch_bounds__(192) conv_mma_kernel(const float* __restrict__ bias)
{
    extern __shared__ __align__(16) __nv_bfloat16 sB[];   // [hl2][n160][BROW]
    int tid = threadIdx.x;
    int warp = tid >> 5, lane = tid & 31;
    int y0 = blockIdx.x * 4, z = blockIdx.y, b = blockIdx.z;
    int m0 = warp * 16;
    int r = lane >> 2, cc = (lane & 3) * 2;

    float C[20][4];
    #pragma unroll
    for (int t = 0; t < 20; t++)
        #pragma unroll
        for (int j = 0; j < 4; j++) C[t][j] = 0.f;

    for (int tap = 0; tap < 27; tap++) {
        int dz = tap/9, rr = tap - dz*9, dy = rr/3, dx = rr - dy*3;
        int zz = (z + dz + 39) % 40;
        size_t pbase = (((size_t)b*40 + zz)*42)*42*96;

        __syncthreads();
        for (int cidx = tid; cidx < 3840; cidx += 192) {
            int hl = cidx / 1920, r2 = cidx - hl*1920;
            int n = r2 / 12, seg = r2 - n*12;
            int yi = n / 40, x = n - yi*40;
            const __nv_bfloat16* gsrc = (hl ? g_cTL : g_cTH)
                + pbase + ((size_t)(y0 + yi + dy)*42 + (x + dx))*96 + seg*8;
            *(uint4*)&sB[(hl*160 + n)*BROW + seg*8] = *(const uint4*)gsrc;
        }
        __syncthreads();

        const __nv_bfloat16* WH = g_wTH + (size_t)tap*9216;
        const __nv_bfloat16* WL = g_wTL + (size_t)tap*9216;
        #pragma unroll 1
        for (int k = 0; k < 96; k += 16) {
            uint32_t ah[4], al[4];
            {
                const __nv_bfloat16* wb = WH + (m0 + r)*96 + k + cc;
                ah[0] = *(const uint32_t*)(wb);
                ah[1] = *(const uint32_t*)(wb + 8*96);
                ah[2] = *(const uint32_t*)(wb + 8);
                ah[3] = *(const uint32_t*)(wb + 8*96 + 8);
                const __nv_bfloat16* wl = WL + (m0 + r)*96 + k + cc;
                al[0] = *(const uint32_t*)(wl);
                al[1] = *(const uint32_t*)(wl + 8*96);
                al[2] = *(const uint32_t*)(wl + 8);
                al[3] = *(const uint32_t*)(wl + 8*96 + 8);
            }
            #pragma unroll
            for (int t = 0; t < 20; t++) {
                const __nv_bfloat16* bp = &sB[(t*8 + r)*BROW + k + cc];
                uint32_t bh0 = *(const uint32_t*)bp;
                uint32_t bh1 = *(const uint32_t*)(bp + 8);
                uint32_t bl0 = *(const uint32_t*)(bp + 160*BROW);
                uint32_t bl1 = *(const uint32_t*)(bp + 160*BROW + 8);
                mma16816(C[t], ah, bh0, bh1);
                mma16816(C[t], al, bh0, bh1);
                mma16816(C[t], ah, bl0, bl1);
            }
        }
    }

    // epilogue: C(16x8 per tile) + bias -> g_tmp1
    float bv0 = bias[m0 + r];
    float bv1 = bias[m0 + r + 8];
    float* ob0 = &g_tmp1[((size_t)(b*NC + m0 + r)*40 + z)*1600];
    float* ob1 = ob0 + (size_t)8*SP;
    #pragma unroll
    for (int t = 0; t < 20; t++) {
        int n = t*8 + cc;
        int yi = n / 40, x = n - yi*40;
        int off = (y0 + yi)*40 + x;
        *(float2*)(ob0 + off) = make_float2(C[t][0] + bv0, C[t][1] + bv0);
        *(float2*)(ob1 + off) = make_float2(C[t][2] + bv1, C[t][3] + bv1);
    }
}

// -------- instance-norm stats --------
__global__ void __launch_bounds__(512) stats_kernel(int sel)
{
    const float* src = sel ? g_t2 : g_tmp1;
    float* mu = sel ? g_mu2 : g_mu1;
    float* rs = sel ? g_rs2 : g_rs1;
    int bc = blockIdx.x, tid = threadIdx.x;
    const float4* p = (const float4*)(src + (size_t)bc*SP);
    float s = 0.f, s2 = 0.f;
    for (int i = tid; i < SP/4; i += 512) {
        float4 v = p[i];
        s  += v.x + v.y + v.z + v.w;
        s2 += v.x*v.x + v.y*v.y + v.z*v.z + v.w*v.w;
    }
    for (int o = 16; o > 0; o >>= 1) {
        s  += __shfl_down_sync(0xffffffffu, s,  o);
        s2 += __shfl_down_sync(0xffffffffu, s2, o);
    }
    __shared__ float sh[2][16];
    int w = tid >> 5, l = tid & 31;
    if (l == 0) { sh[0][w] = s; sh[1][w] = s2; }
    __syncthreads();
    if (tid == 0) {
        float ts = 0.f, ts2 = 0.f;
        for (int i = 0; i < 16; i++) { ts += sh[0][i]; ts2 += sh[1][i]; }
        float m = ts * (1.0f/SP);
        float var = ts2 * (1.0f/SP) - m*m;
        mu[bc] = m; rs[bc] = rsqrtf(var + 1e-5f);
    }
}

// -------- pointwise GEMM with fused transforms --------
template<int MODE>
__global__ void __launch_bounds__(256) pw_kernel(const float* __restrict__ W,
                                                 const float* __restrict__ bias,
                                                 const float* __restrict__ xin,
                                                 float* __restrict__ outp)
{
    __shared__ __align__(16) float s_in[32*128];
    __shared__ float s_w [32*97];
    int t = blockIdx.x, b = t / 500, v0 = (t - b*500)*128;
    int gy = blockIdx.y, tid = threadIdx.x;
    const float* in = (MODE==0) ? g_tmp1 : (MODE==1) ? g_t2 : (MODE==2) ? g_xmod : g_osum;
    const float* Wp = (MODE==0) ? g_Wc : W;
    const float* bp = (MODE==0) ? g_bc : bias;
    const float* mu = (MODE==0) ? g_mu1 : g_mu2;
    const float* rs = (MODE==0) ? g_rs1 : g_rs2;
    ull acc[6][4];
    #pragma unroll
    for (int i = 0; i < 6; i++)
        #pragma unroll
        for (int j = 0; j < 4; j++) acc[i][j] = 0ull;
    int ocg = tid >> 4, vb = (tid & 15)*8;
    for (int kc = 0; kc < 3; kc++) {
        __syncthreads();
        for (int idx = tid; idx < 32*128; idx += 256) {
            int cil = idx >> 7, vv = idx & 127;
            int ci = kc*32 + cil;
            float val = in[((size_t)(b*NC + ci))*SP + v0 + vv];
            if (MODE == 0 || MODE == 1) {
                val = (val - mu[b*NC + ci]) * rs[b*NC + ci];
                val = gelu_f(val);
            }
            s_in[cil*128 + vv] = val;
        }
        for (int idx = tid; idx < 32*96; idx += 256) {
            int oc = idx >> 5, cil = idx & 31;
            s_w[cil*97 + oc] = Wp[(size_t)(gy*NC + oc)*NC + kc*32 + cil];
        }
        __syncthreads();
        #pragma unroll 4
        for (int kl = 0; kl < 32; kl++) {
            ull A[6];
            #pragma unroll
            for (int i = 0; i < 6; i++) { float av = s_w[kl*97 + ocg + 16*i]; A[i] = pack2(av, av); }
            const ulonglong2* bp2 = (const ulonglong2*)&s_in[kl*128 + vb];
            ulonglong2 b01 = bp2[0], b23 = bp2[1];
            #pragma unroll
            for (int i = 0; i < 6; i++) {
                acc[i][0] = fma2(A[i], b01.x, acc[i][0]);
                acc[i][1] = fma2(A[i], b01.y, acc[i][1]);
                acc[i][2] = fma2(A[i], b23.x, acc[i][2]);
                acc[i][3] = fma2(A[i], b23.y, acc[i][3]);
            }
        }
    }
    #pragma unroll
    for (int i = 0; i < 6; i++) {
        int oc = ocg + 16*i, goc = gy*NC + oc;
        float bb = bp[goc];
        #pragma unroll
        for (int jp = 0; jp < 4; jp++) {
            float2 f = asf2(acc[i][jp]);
            float rv[2] = {f.x + bb, f.y + bb};
            #pragma unroll
            for (int h = 0; h < 2; h++) {
                float r = rv[h];
                size_t vidx = (size_t)v0 + vb + jp*2 + h;
                if (MODE == 0) g_t2[((size_t)(b*NC + oc))*SP + vidx] = r;
                else if (MODE == 1) {
                    float m = 1.0f / (1.0f + expf(-r));
                    size_t o = ((size_t)(b*NC + oc))*SP + vidx;
                    g_xmod[o] = xin[o] * m;
                } else if (MODE == 2) {
                    if (goc < NC) r *= 0.20412414523193154f;
                    g_qkv[((size_t)(b*3*NC + goc))*SP + vidx] = r;
                } else outp[((size_t)(b*NC + oc))*SP + vidx] = r;
            }
        }
    }
}

// -------- transposes --------
__global__ void __launch_bounds__(256) tr_d_kernel(const float* __restrict__ in, float* __restrict__ out)
{
    __shared__ float tile[40*33];
    int m0 = blockIdx.x*32; size_t base = (size_t)blockIdx.y*SP; int tid = threadIdx.x;
    for (int i = tid; i < 1280; i += 256) { int z = i>>5, mm = i&31; tile[z*33+mm] = in[base + (size_t)z*1600 + m0 + mm]; }
    __syncthreads();
    for (int i = tid; i < 1280; i += 256) { int mm = i/40, z = i - mm*40; out[base + (size_t)(m0+mm)*40 + z] = tile[z*33+mm]; }
}
__global__ void __launch_bounds__(256) trb_d_kernel(const float* __restrict__ oT, float* __restrict__ osum)
{
    __shared__ float tile[40*33];
    int m0 = blockIdx.x*32; size_t base = (size_t)blockIdx.y*SP; int tid = threadIdx.x;
    for (int i = tid; i < 1280; i += 256) { int mm = i/40, z = i - mm*40; tile[z*33+mm] = oT[base + (size_t)(m0+mm)*40 + z]; }
    __syncthreads();
    for (int i = tid; i < 1280; i += 256) { int z = i>>5, mm = i&31; osum[base + (size_t)z*1600 + m0 + mm] += tile[z*33+mm]; }
}
__global__ void __launch_bounds__(256) tr_h_kernel(const float* __restrict__ in, float* __restrict__ out)
{
    __shared__ float tile[40*41];
    int z = blockIdx.x; size_t base = (size_t)blockIdx.y*SP; int tid = threadIdx.x;
    for (int i = tid; i < 1600; i += 256) { int y = i/40, x = i - y*40; tile[y*41+x] = in[base + (size_t)z*1600 + y*40 + x]; }
    __syncthreads();
    for (int i = tid; i < 1600; i += 256) { int x = i/40, y = i - x*40; out[base + ((size_t)z*40 + x)*40 + y] = tile[y*41+x]; }
}
__global__ void __launch_bounds__(256) trb_h_kernel(const float* __restrict__ oT, float* __restrict__ osum)
{
    __shared__ float tile[40*41];
    int z = blockIdx.x; size_t base = (size_t)blockIdx.y*SP; int tid = threadIdx.x;
    for (int i = tid; i < 1600; i += 256) { int x = i/40, y = i - x*40; tile[y*41+x] = oT[base + ((size_t)z*40 + x)*40 + y]; }
    __syncthreads();
    for (int i = tid; i < 1600; i += 256) { int y = i/40, x = i - y*40; osum[base + (size_t)z*1600 + y*40 + x] += tile[y*41+x]; }
}

// -------- axial attention (register-resident q/S) --------
__global__ void __launch_bounds__(40*LPB) attn_kernel(const float* __restrict__ src, float* __restrict__ dst)
{
    __shared__ __align__(16) float skv[2][LPB][40*26];
    int b = blockIdx.z, head = blockIdx.y, line0 = blockIdx.x*LPB;
    int tid = threadIdx.x, ll = tid/40, i = tid%40;
    for (int idx = tid; idx < 2*LPB*240; idx += 40*LPB) {
        int w_ = idx / (LPB*240), r = idx - w_*(LPB*240);
        int l_ = r/240, r2 = r - l_*240, dd = r2/10, seg = r2 - dd*10;
        const float* p = src + ((size_t)(b*288 + (w_+1)*96 + head*NHD + dd))*SP + (size_t)(line0+l_)*40 + seg*4;
        float4 v4 = *(const float4*)p;
        float* d = &skv[w_][l_][0];
        int l4 = seg*4;
        d[(l4+0)*26+dd] = v4.x; d[(l4+1)*26+dd] = v4.y; d[(l4+2)*26+dd] = v4.z; d[(l4+3)*26+dd] = v4.w;
    }
    ull qr[12];
    {
        const float* qp = src + ((size_t)(b*288 + head*NHD))*SP + (size_t)(line0+ll)*40 + i;
        #pragma unroll
        for (int dp = 0; dp < 12; dp++) qr[dp] = pack2(qp[(size_t)(2*dp)*SP], qp[(size_t)(2*dp+1)*SP]);
    }
    __syncthreads();
    float S[40];
    {
        const float* kb = &skv[0][ll][0];
        #pragma unroll 4
        for (int j = 0; j < 40; j++) {
            ull acc = 0ull;
            #pragma unroll
            for (int dp = 0; dp < 12; dp++) acc = fma2(qr[dp], *(const ull*)&kb[j*26 + 2*dp], acc);
            float2 f = asf2(acc);
            S[j] = f.x + f.y;
        }
    }
    float m = -1e30f;
    #pragma unroll 8
    for (int j = 0; j < 40; j++) m = fmaxf(m, S[j]);
    float sum = 0.f;
    #pragma unroll 8
    for (int j = 0; j < 40; j++) { float e = __expf(S[j] - m); S[j] = e; sum += e; }
    float inv = 1.0f / sum;
    ull o[12];
    #pragma unroll
    for (int dp = 0; dp < 12; dp++) o[dp] = 0ull;
    {
        const float* vb = &skv[1][ll][0];
        #pragma unroll 4
        for (int j = 0; j < 40; j++) {
            ull sj = pack2(S[j], S[j]);
            #pragma unroll
            for (int dp = 0; dp < 12; dp++) o[dp] = fma2(sj, *(const ull*)&vb[j*26 + 2*dp], o[dp]);
        }
    }
    size_t ob = ((size_t)(b*NC + head*NHD))*SP + (size_t)(line0+ll)*40 + i;
    #pragma unroll
    for (int dp = 0; dp < 12; dp++) {
        float2 f = asf2(o[dp]);
        dst[ob + (size_t)(2*dp)*SP]   = f.x * inv;
        dst[ob + (size_t)(2*dp+1)*SP] = f.y * inv;
    }
}

// -------- launch --------
extern "C" void kernel_launch(void* const* d_in, const int* in_sizes, int n_in,
                              void* d_out, int out_size)
{
    const float* x      = (const float*)d_in[0];
    const float* pos    = (const float*)d_in[1];
    const float* qkv_w  = (const float*)d_in[2];
    const float* qkv_b  = (const float*)d_in[3];
    const float* lp1_w  = (const float*)d_in[4];
    const float* lp1_b  = (const float*)d_in[5];
    const float* lp2_w  = (const float*)d_in[6];
    const float* lp2_b  = (const float*)d_in[7];
    const float* mod1_w = (const float*)d_in[8];
    const float* mod1_b = (const float*)d_in[9];
    const float* mod2_w = (const float*)d_in[10];
    const float* mod2_b = (const float*)d_in[11];
    // d_in[12..16]: pa_w, pa_b, R6_d/h/w -- mathematically dead
    const float* proj_w = (const float*)d_in[17];
    const float* proj_b = (const float*)d_in[18];
    float* out = (float*)d_out;

    const int CONV_SMEM = 2*160*BROW*2;   // 66560 B
    cudaFuncSetAttribute(conv_mma_kernel, cudaFuncAttributeMaxDynamicSharedMemorySize, CONV_SMEM);

    prep_wc_kernel<<<96, 96>>>(mod1_w, lp2_w, lp2_b, mod1_b);
    prep_wT_kernel<<<(27*96*96 + 255)/256, 256>>>(lp1_w);
    prep_cT_kernel<<<dim3(42, 40, NB), 256>>>(pos);

    conv_mma_kernel<<<dim3(10, 40, NB), 192, CONV_SMEM>>>(lp1_b);

    stats_kernel<<<NB*NC, 512>>>(0);
    pw_kernel<0><<<dim3(1000, 1), 256>>>(nullptr, nullptr, nullptr, nullptr);
    stats_kernel<<<NB*NC, 512>>>(1);
    pw_kernel<1><<<dim3(1000, 1), 256>>>(mod2_w, mod2_b, x, nullptr);
    pw_kernel<2><<<dim3(1000, 3), 256>>>(qkv_w, qkv_b, nullptr, nullptr);

    float *qTd, *qTh, *qkvp, *oTd, *oTh, *osum;
    cudaGetSymbolAddress((void**)&qTd, g_qTd);
    cudaGetSymbolAddress((void**)&qTh, g_qTh);
    cudaGetSymbolAddress((void**)&qkvp, g_qkv);
    cudaGetSymbolAddress((void**)&oTd, g_tmp1);
    cudaGetSymbolAddress((void**)&oTh, g_t2);
    cudaGetSymbolAddress((void**)&osum, g_osum);

    tr_d_kernel<<<dim3(50, NB*3*NC), 256>>>(qkvp, qTd);
    tr_h_kernel<<<dim3(40, NB*3*NC), 256>>>(qkvp, qTh);

    attn_kernel<<<dim3(1600/LPB, NHEADS, NB), 40*LPB>>>(qkvp, osum);
    attn_kernel<<<dim3(1600/LPB, NHEADS, NB), 40*LPB>>>(qTd, oTd);
    attn_kernel<<<dim3(1600/LPB, NHEADS, NB), 40*LPB>>>(qTh, oTh);

    trb_d_kernel<<<dim3(50, NB*NC), 256>>>(oTd, osum);
    trb_h_kernel<<<dim3(40, NB*NC), 256>>>(oTh, osum);

    pw_kernel<3><<<dim3(1000, 1), 256>>>(proj_w, proj_b, nullptr, out);
}